// round 6
// baseline (speedup 1.0000x reference)
#include <cuda_runtime.h>
#include <cuda_fp16.h>

// PPISP pipeline. Round 6: 4 points/thread (two pairs), float4/int4 streaming,
// pairwise float2 output stores (low live-output regs), all tables in smem.
// launch_bounds(256,5) -> <=51 regs, 40 warps/SM.
//
// Tables (K1):
//   g_q[f] = float4 {m00, m11, m22, bits(h2(m01,m02))}   (diag fp32)
//   g_u[f] = uint2  {bits(h2(m10,m12)), bits(h2(m20,m21))}
//   g_Pa[j*4+c] = float4 {h2(v0,v1), h2(p2,p3), h2(p4,d), a(fp32)}
//   g_HC[c]     = float4 {h2(hc0,hb0), h2(hc1,hb1), h2(hc2,hb2), 0}
//     hc = 0.5/c_crf, hb = 0.5*b ; out = hb + hb*tanh((xp-d)*hc)

#define MAX_F 4096

__device__ float4 g_q[MAX_F];
__device__ uint2  g_u[MAX_F];
__device__ __align__(128) float4 g_Pa[3 * 4];   // [j][c]
__device__ __align__(64)  float4 g_HC[4];

__device__ __forceinline__ unsigned int f2h2(float a, float b) {
    __half2 h = __floats2half2_rn(a, b);
    return *reinterpret_cast<unsigned int*>(&h);
}
__device__ __forceinline__ float2 h22f2(unsigned int u) {
    __half2 h = *reinterpret_cast<__half2*>(&u);
    return __half22float2(h);
}

__global__ void ppisp_precompute(const float* __restrict__ expo,
                                 const float* __restrict__ vig,
                                 const float* __restrict__ colp,
                                 const float* __restrict__ crf,
                                 int F, int C)
{
    int t = blockIdx.x * blockDim.x + threadIdx.x;
    if (t < F) {
        float e  = exp2f(expo[t]);
        const float* cp = colp + t * 8;
        float s0 = e * expf(cp[0]);
        float s1 = e;
        float s2 = e * expf(cp[1]);
        float o0 = cp[2], o1 = cp[3], o2 = cp[4];
        float o3 = cp[5], o4 = cp[6], o5 = cp[7];
        float m00 = (1.0f - o0 - o1) * s0, m01 = o0 * s1, m02 = o1 * s2;
        float m10 = o2 * s0, m11 = (1.0f - o2 - o3) * s1, m12 = o3 * s2;
        float m20 = o4 * s0, m21 = o5 * s1, m22 = (1.0f - o4 - o5) * s2;
        float4 q;
        q.x = m00; q.y = m11; q.z = m22;
        q.w = __uint_as_float(f2h2(m01, m02));
        g_q[t] = q;
        g_u[t] = make_uint2(f2h2(m10, m12), f2h2(m20, m21));
    }
    if (blockIdx.x == 0 && (int)threadIdx.x < C * 3 && (int)threadIdx.x < 12) {
        int c = threadIdx.x / 3;
        int j = threadIdx.x % 3;
        const float* vp = vig + c * 15 + j * 5;
        const float* kp = crf + c * 12 + j * 4;
        float a = log1pf(expf(kp[0])) + 0.3f;   // accurate softplus (once)
        float d = kp[3];
        float4 P;
        P.x = __uint_as_float(f2h2(vp[0], vp[1]));
        P.y = __uint_as_float(f2h2(vp[2], vp[3]));
        P.z = __uint_as_float(f2h2(vp[4], d));
        P.w = a;
        g_Pa[j * 4 + c] = P;
    }
    if (blockIdx.x == 0 && (int)threadIdx.x < C && (int)threadIdx.x < 4) {
        int c = threadIdx.x;
        const float* kp = crf + c * 12;
        float4 H; float* Hf = (float*)&H;
#pragma unroll
        for (int j = 0; j < 3; j++) {
            float b  = log1pf(expf(kp[4 * j + 1])) + 0.3f;
            float cc = log1pf(expf(kp[4 * j + 2])) + 0.1f;
            Hf[j] = __uint_as_float(f2h2(0.5f / cc, 0.5f * b));
        }
        Hf[3] = 0.0f;
        g_HC[c] = H;
    }
}

__device__ __forceinline__ float fast_lg2(float x) {
    float y; asm("lg2.approx.f32 %0, %1;" : "=f"(y) : "f"(x)); return y;
}
__device__ __forceinline__ float fast_ex2(float x) {
    float y; asm("ex2.approx.f32 %0, %1;" : "=f"(y) : "f"(x)); return y;
}
__device__ __forceinline__ float fast_tanh(float x) {
    float y; asm("tanh.approx.f32 %0, %1;" : "=f"(y) : "f"(x)); return y;
}

__device__ __forceinline__ void process_point(
    float r, float g, float b, float px, float py, int c, int f,
    float invW2, float invH2,
    const float4* __restrict__ s_q, const uint2* __restrict__ s_u,
    const float4* __restrict__ s_Pa, const float4* __restrict__ s_HC,
    float* __restrict__ o)
{
    float4 q  = s_q[f];
    uint2  uo = s_u[f];
    float2 m0102 = h22f2(__float_as_uint(q.w));
    float2 m1012 = h22f2(uo.x);
    float2 m2021 = h22f2(uo.y);

    float u = fmaf(px, invW2, -1.0f);
    float v = fmaf(py, invH2, -1.0f);

    float rgbv[3] = {r, g, b};
    float t[3], aj[3], dj[3];
#pragma unroll
    for (int j = 0; j < 3; j++) {
        float4 P = s_Pa[j * 4 + c];
        float2 v01 = h22f2(__float_as_uint(P.x));
        float2 p23 = h22f2(__float_as_uint(P.y));
        float2 p4d = h22f2(__float_as_uint(P.z));
        float du = u - v01.x;
        float dv = v - v01.y;
        float r2 = fmaf(du, du, dv * dv);
        float gn = fmaf(r2, fmaf(r2, fmaf(r2, p4d.x, p23.y), p23.x), 1.0f);
        t[j] = rgbv[j] * gn;
        aj[j] = P.w;
        dj[j] = p4d.y;
    }

    float y[3];
    y[0] = fmaf(q.x,     t[0], fmaf(m0102.x, t[1], m0102.y * t[2]));
    y[1] = fmaf(m1012.x, t[0], fmaf(q.y,     t[1], m1012.y * t[2]));
    y[2] = fmaf(m2021.x, t[0], fmaf(m2021.y, t[1], q.z     * t[2]));

    float4 HC = s_HC[c];
    const float* Hf = (const float*)&HC;
#pragma unroll
    for (int j = 0; j < 3; j++) {
        float2 hcb = h22f2(__float_as_uint(Hf[j]));
        float xp  = fast_ex2(aj[j] * fast_lg2(fmaxf(y[j], 1e-6f)));
        float arg = (xp - dj[j]) * hcb.x;
        o[j] = fmaf(hcb.y, fast_tanh(arg), hcb.y);
    }
}

__global__ void __launch_bounds__(256, 5)
ppisp_main(const float* __restrict__ rgb,
           const float* __restrict__ coords,
           const int*   __restrict__ cam,
           const int*   __restrict__ frm,
           const int*   __restrict__ pW,
           const int*   __restrict__ pH,
           float* __restrict__ out,
           int B, int F)
{
    extern __shared__ float4 smbase[];
    float4* s_q  = smbase;                  // [F] 16B
    float4* s_Pa = s_q + F;                 // [12]
    float4* s_HC = s_Pa + 12;               // [4]
    uint2*  s_u  = (uint2*)(s_HC + 4);      // [F] 8B

    for (int i = threadIdx.x; i < F; i += blockDim.x) {
        s_q[i] = g_q[i];
        s_u[i] = g_u[i];
    }
    if (threadIdx.x < 12) s_Pa[threadIdx.x] = g_Pa[threadIdx.x];
    if (threadIdx.x < 4)  s_HC[threadIdx.x] = g_HC[threadIdx.x];
    __syncthreads();

    float invW2 = 2.0f / (float)__ldg(pW);
    float invH2 = 2.0f / (float)__ldg(pH);

    int nQ = (B + 3) >> 2;   // quads of points
    for (int t = blockIdx.x * blockDim.x + threadIdx.x; t < nQ;
         t += gridDim.x * blockDim.x) {
        int i0 = t * 4;
        if (i0 + 3 < B) {
            const float4* rgb4 = (const float4*)rgb;
            const float4* pc4  = (const float4*)coords;
            float4 ra = rgb4[3 * t + 0];
            float4 rb = rgb4[3 * t + 1];
            float4 rc = rgb4[3 * t + 2];
            float4 pa = pc4[2 * t + 0];
            float4 pb = pc4[2 * t + 1];
            int4 c4 = ((const int4*)cam)[t];
            int4 f4 = ((const int4*)frm)[t];

            float2* O = (float2*)out;
            float o[6];

            // pair 1: points 0,1
            process_point(ra.x, ra.y, ra.z, pa.x, pa.y, c4.x, f4.x,
                          invW2, invH2, s_q, s_u, s_Pa, s_HC, o + 0);
            process_point(ra.w, rb.x, rb.y, pa.z, pa.w, c4.y, f4.y,
                          invW2, invH2, s_q, s_u, s_Pa, s_HC, o + 3);
            O[6 * t + 0] = make_float2(o[0], o[1]);
            O[6 * t + 1] = make_float2(o[2], o[3]);
            O[6 * t + 2] = make_float2(o[4], o[5]);

            // pair 2: points 2,3
            process_point(rb.z, rb.w, rc.x, pb.x, pb.y, c4.z, f4.z,
                          invW2, invH2, s_q, s_u, s_Pa, s_HC, o + 0);
            process_point(rc.y, rc.z, rc.w, pb.z, pb.w, c4.w, f4.w,
                          invW2, invH2, s_q, s_u, s_Pa, s_HC, o + 3);
            O[6 * t + 3] = make_float2(o[0], o[1]);
            O[6 * t + 4] = make_float2(o[2], o[3]);
            O[6 * t + 5] = make_float2(o[4], o[5]);
        } else {
            for (int i = i0; i < B; i++) {
                float o[3];
                process_point(rgb[3 * i], rgb[3 * i + 1], rgb[3 * i + 2],
                              coords[2 * i], coords[2 * i + 1],
                              cam[i], frm[i], invW2, invH2,
                              s_q, s_u, s_Pa, s_HC, o);
                out[3 * i + 0] = o[0];
                out[3 * i + 1] = o[1];
                out[3 * i + 2] = o[2];
            }
        }
    }
}

extern "C" void kernel_launch(void* const* d_in, const int* in_sizes, int n_in,
                              void* d_out, int out_size) {
    const float* expo   = (const float*)d_in[0];
    const float* vig    = (const float*)d_in[1];
    const float* colp   = (const float*)d_in[2];
    const float* crf    = (const float*)d_in[3];
    const float* rgb    = (const float*)d_in[4];
    const float* coords = (const float*)d_in[5];
    const int*   cam    = (const int*)d_in[6];
    const int*   frm    = (const int*)d_in[7];
    const int*   pW     = (const int*)d_in[8];
    const int*   pH     = (const int*)d_in[9];
    float* out = (float*)d_out;

    int F = in_sizes[0];
    int C = in_sizes[1] / 15;
    int B = in_sizes[6];
    if (F > MAX_F) F = MAX_F;   // table capacity guard (problem uses F=1000)

    // s_q[F] + s_Pa[12] + s_HC[4] + s_u[F]
    size_t shmem = (size_t)F * 16 + 16 * 16 + (size_t)F * 8;

    {
        int pthreads = 256;
        int pwork = (F > C * 3) ? F : C * 3;
        int pblocks = (pwork + pthreads - 1) / pthreads;
        ppisp_precompute<<<pblocks, pthreads>>>(expo, vig, colp, crf, F, C);
    }

    static bool attr_done = false;
    if (!attr_done) {
        cudaFuncSetAttribute(ppisp_main,
                             cudaFuncAttributeMaxDynamicSharedMemorySize,
                             (int)shmem > 49152 ? (int)shmem : 49152);
        attr_done = true;
    }

    int nQ = (B + 3) / 4;
    int blocks = (nQ + 255) / 256;
    int maxb = 148 * 5;
    if (blocks > maxb) blocks = maxb;
    ppisp_main<<<blocks, 256, shmem>>>(rgb, coords, cam, frm, pW, pH,
                                       out, B, F);
}

// round 7
// speedup vs baseline: 1.1799x; 1.1799x over previous
#include <cuda_runtime.h>
#include <cuda_fp16.h>

// PPISP pipeline. Round 7: 1 point/thread, max occupancy (<=32 regs,
// 8 blocks/SM = 64 warps), all tables staged in smem (24.25 KB/block).
// R6 lesson: warp count beats per-thread ILP on this latency-bound kernel.
//
// Tables (K1):
//   g_q[f] = float4 {m00, m11, m22, bits(h2(m01,m02))}   (diag fp32)
//   g_u[f] = uint2  {bits(h2(m10,m12)), bits(h2(m20,m21))}
//   g_Pa[j*4+c] = float4 {h2(v0,v1), h2(p2,p3), h2(p4,d), a(fp32)}
//   g_HC[c]     = float4 {h2(hc0,hb0), h2(hc1,hb1), h2(hc2,hb2), 0}
//     hc = 0.5/c_crf, hb = 0.5*b ; out = hb + hb*tanh((xp-d)*hc)

#define MAX_F 4096

__device__ float4 g_q[MAX_F];
__device__ uint2  g_u[MAX_F];
__device__ __align__(128) float4 g_Pa[3 * 4];   // [j][c]
__device__ __align__(64)  float4 g_HC[4];

__device__ __forceinline__ unsigned int f2h2(float a, float b) {
    __half2 h = __floats2half2_rn(a, b);
    return *reinterpret_cast<unsigned int*>(&h);
}
__device__ __forceinline__ float2 h22f2(unsigned int u) {
    __half2 h = *reinterpret_cast<__half2*>(&u);
    return __half22float2(h);
}

__global__ void ppisp_precompute(const float* __restrict__ expo,
                                 const float* __restrict__ vig,
                                 const float* __restrict__ colp,
                                 const float* __restrict__ crf,
                                 int F, int C)
{
    int t = blockIdx.x * blockDim.x + threadIdx.x;
    if (t < F) {
        float e  = exp2f(expo[t]);
        const float* cp = colp + t * 8;
        float s0 = e * expf(cp[0]);
        float s1 = e;
        float s2 = e * expf(cp[1]);
        float o0 = cp[2], o1 = cp[3], o2 = cp[4];
        float o3 = cp[5], o4 = cp[6], o5 = cp[7];
        float m00 = (1.0f - o0 - o1) * s0, m01 = o0 * s1, m02 = o1 * s2;
        float m10 = o2 * s0, m11 = (1.0f - o2 - o3) * s1, m12 = o3 * s2;
        float m20 = o4 * s0, m21 = o5 * s1, m22 = (1.0f - o4 - o5) * s2;
        float4 q;
        q.x = m00; q.y = m11; q.z = m22;
        q.w = __uint_as_float(f2h2(m01, m02));
        g_q[t] = q;
        g_u[t] = make_uint2(f2h2(m10, m12), f2h2(m20, m21));
    }
    if (blockIdx.x == 0 && (int)threadIdx.x < C * 3 && (int)threadIdx.x < 12) {
        int c = threadIdx.x / 3;
        int j = threadIdx.x % 3;
        const float* vp = vig + c * 15 + j * 5;
        const float* kp = crf + c * 12 + j * 4;
        float a = log1pf(expf(kp[0])) + 0.3f;   // accurate softplus (once)
        float d = kp[3];
        float4 P;
        P.x = __uint_as_float(f2h2(vp[0], vp[1]));
        P.y = __uint_as_float(f2h2(vp[2], vp[3]));
        P.z = __uint_as_float(f2h2(vp[4], d));
        P.w = a;
        g_Pa[j * 4 + c] = P;
    }
    if (blockIdx.x == 0 && (int)threadIdx.x < C && (int)threadIdx.x < 4) {
        int c = threadIdx.x;
        const float* kp = crf + c * 12;
        float4 H; float* Hf = (float*)&H;
#pragma unroll
        for (int j = 0; j < 3; j++) {
            float b  = log1pf(expf(kp[4 * j + 1])) + 0.3f;
            float cc = log1pf(expf(kp[4 * j + 2])) + 0.1f;
            Hf[j] = __uint_as_float(f2h2(0.5f / cc, 0.5f * b));
        }
        Hf[3] = 0.0f;
        g_HC[c] = H;
    }
}

__device__ __forceinline__ float fast_lg2(float x) {
    float y; asm("lg2.approx.f32 %0, %1;" : "=f"(y) : "f"(x)); return y;
}
__device__ __forceinline__ float fast_ex2(float x) {
    float y; asm("ex2.approx.f32 %0, %1;" : "=f"(y) : "f"(x)); return y;
}
__device__ __forceinline__ float fast_tanh(float x) {
    float y; asm("tanh.approx.f32 %0, %1;" : "=f"(y) : "f"(x)); return y;
}

__global__ void __launch_bounds__(256, 8)
ppisp_main(const float* __restrict__ rgb,
           const float* __restrict__ coords,
           const int*   __restrict__ cam,
           const int*   __restrict__ frm,
           const int*   __restrict__ pW,
           const int*   __restrict__ pH,
           float* __restrict__ out,
           int B, int F)
{
    extern __shared__ float4 smbase[];
    float4* s_q  = smbase;                  // [F] 16B
    float4* s_Pa = s_q + F;                 // [12]
    float4* s_HC = s_Pa + 12;               // [4]
    uint2*  s_u  = (uint2*)(s_HC + 4);      // [F] 8B

    for (int i = threadIdx.x; i < F; i += blockDim.x) {
        s_q[i] = g_q[i];
        s_u[i] = g_u[i];
    }
    if (threadIdx.x < 12) s_Pa[threadIdx.x] = g_Pa[threadIdx.x];
    if (threadIdx.x < 4)  s_HC[threadIdx.x] = g_HC[threadIdx.x];
    __syncthreads();

    float invW2 = 2.0f / (float)__ldg(pW);
    float invH2 = 2.0f / (float)__ldg(pH);

    for (int i = blockIdx.x * blockDim.x + threadIdx.x; i < B;
         i += gridDim.x * blockDim.x) {
        float r  = rgb[3 * i + 0];
        float g  = rgb[3 * i + 1];
        float b  = rgb[3 * i + 2];
        float px = coords[2 * i + 0];
        float py = coords[2 * i + 1];
        int   c  = cam[i];
        int   f  = frm[i];

        float u = fmaf(px, invW2, -1.0f);
        float v = fmaf(py, invH2, -1.0f);

        float rgbv[3] = {r, g, b};
        float t[3], aj[3], dj[3];
#pragma unroll
        for (int j = 0; j < 3; j++) {
            float4 P = s_Pa[j * 4 + c];
            float2 v01 = h22f2(__float_as_uint(P.x));
            float2 p23 = h22f2(__float_as_uint(P.y));
            float2 p4d = h22f2(__float_as_uint(P.z));
            float du = u - v01.x;
            float dv = v - v01.y;
            float r2 = fmaf(du, du, dv * dv);
            float gn = fmaf(r2, fmaf(r2, fmaf(r2, p4d.x, p23.y), p23.x), 1.0f);
            t[j] = rgbv[j] * gn;
            aj[j] = P.w;
            dj[j] = p4d.y;
        }

        float4 q  = s_q[f];
        uint2  uo = s_u[f];
        float2 m0102 = h22f2(__float_as_uint(q.w));
        float2 m1012 = h22f2(uo.x);
        float2 m2021 = h22f2(uo.y);

        float y0 = fmaf(q.x,     t[0], fmaf(m0102.x, t[1], m0102.y * t[2]));
        float y1 = fmaf(m1012.x, t[0], fmaf(q.y,     t[1], m1012.y * t[2]));
        float y2 = fmaf(m2021.x, t[0], fmaf(m2021.y, t[1], q.z     * t[2]));
        float yv[3] = {y0, y1, y2};

        float4 HC = s_HC[c];
        const float* Hf = (const float*)&HC;
#pragma unroll
        for (int j = 0; j < 3; j++) {
            float2 hcb = h22f2(__float_as_uint(Hf[j]));
            float xp  = fast_ex2(aj[j] * fast_lg2(fmaxf(yv[j], 1e-6f)));
            float arg = (xp - dj[j]) * hcb.x;
            out[3 * i + j] = fmaf(hcb.y, fast_tanh(arg), hcb.y);
        }
    }
}

extern "C" void kernel_launch(void* const* d_in, const int* in_sizes, int n_in,
                              void* d_out, int out_size) {
    const float* expo   = (const float*)d_in[0];
    const float* vig    = (const float*)d_in[1];
    const float* colp   = (const float*)d_in[2];
    const float* crf    = (const float*)d_in[3];
    const float* rgb    = (const float*)d_in[4];
    const float* coords = (const float*)d_in[5];
    const int*   cam    = (const int*)d_in[6];
    const int*   frm    = (const int*)d_in[7];
    const int*   pW     = (const int*)d_in[8];
    const int*   pH     = (const int*)d_in[9];
    float* out = (float*)d_out;

    int F = in_sizes[0];
    int C = in_sizes[1] / 15;
    int B = in_sizes[6];
    if (F > MAX_F) F = MAX_F;   // table capacity guard (problem uses F=1000)

    // s_q[F] + s_Pa[12] + s_HC[4] + s_u[F]
    size_t shmem = (size_t)F * 16 + 16 * 16 + (size_t)F * 8;

    {
        int pthreads = 256;
        int pwork = (F > C * 3) ? F : C * 3;
        int pblocks = (pwork + pthreads - 1) / pthreads;
        ppisp_precompute<<<pblocks, pthreads>>>(expo, vig, colp, crf, F, C);
    }

    static bool attr_done = false;
    if (!attr_done) {
        cudaFuncSetAttribute(ppisp_main,
                             cudaFuncAttributeMaxDynamicSharedMemorySize,
                             (int)shmem > 49152 ? (int)shmem : 49152);
        attr_done = true;
    }

    int blocks = (B + 255) / 256;
    int maxb = 148 * 8;
    if (blocks > maxb) blocks = maxb;
    ppisp_main<<<blocks, 256, shmem>>>(rgb, coords, cam, frm, pW, pH,
                                       out, B, F);
}